// round 11
// baseline (speedup 1.0000x reference)
#include <cuda_runtime.h>
#include <cuda_fp16.h>
#include <cstdint>

#define BATCH 4096
#define T_STEPS 50
#define HID 256
#define HSTR (T_STEPS * HID)   // out row stride: 12800 floats

// ---------------- scratch (no allocations allowed) ----------------
__device__ float g_xhi[BATCH * 256],  g_xlo[BATCH * 256];
__device__ float g_w1h[512 * 256],    g_w1l[512 * 256];
__device__ float g_w2h[256 * 512],    g_w2l[256 * 512];
__device__ float g_w3h[128 * 256],    g_w3l[128 * 256];
__device__ float g_wihh[1024 * 128],  g_wihl[1024 * 128];
__device__ float g_h1h[BATCH * 512],  g_h1l[BATCH * 512];
__device__ float g_h2h[BATCH * 256],  g_h2l[BATCH * 256];
__device__ float g_z1h[BATCH * 128],  g_z1l[BATCH * 128];
__device__ float g_xp[1024 * BATCH];          // fp32 TRANSPOSED [1024][4096] (incl. biases)
__device__ float g_c [256  * BATCH];          // fp32 TRANSPOSED [256][4096]
__device__ __half g_ht[BATCH * 256];          // fp16 compact h_{t-1}
__device__ __half g_whhc[1024 * 256];         // fp16 permuted Whh: r' = jb8*128 + g*32 + j

// ---------------- helpers ----------------
__device__ __forceinline__ uint32_t f2tf(float x) {
    uint32_t r;
    asm("cvt.rna.tf32.f32 %0, %1;" : "=r"(r) : "f"(x));
    return r;
}
__device__ __forceinline__ float f2tf_f(float x) { return __uint_as_float(f2tf(x)); }
__device__ __forceinline__ uint32_t smem_u32(const void* p) {
    uint32_t a;
    asm("{ .reg .u64 t; cvta.to.shared.u64 t, %1; cvt.u32.u64 %0, t; }" : "=r"(a) : "l"(p));
    return a;
}
__device__ __forceinline__ void cp16(uint32_t d, const void* s) {
    asm volatile("cp.async.cg.shared.global [%0], [%1], 16;" :: "r"(d), "l"(s));
}
__device__ __forceinline__ void cp_commit() { asm volatile("cp.async.commit_group;"); }
__device__ __forceinline__ void cp_wait1()  { asm volatile("cp.async.wait_group 1;" ::: "memory"); }
__device__ __forceinline__ void cp_wait0()  { asm volatile("cp.async.wait_group 0;" ::: "memory"); }
__device__ __forceinline__ void mma8(float* c, const uint32_t* a, const uint32_t* b) {
    asm volatile(
        "mma.sync.aligned.m16n8k8.row.col.f32.tf32.tf32.f32 "
        "{%0,%1,%2,%3}, {%4,%5,%6,%7}, {%8,%9}, {%0,%1,%2,%3};"
        : "+f"(c[0]), "+f"(c[1]), "+f"(c[2]), "+f"(c[3])
        : "r"(a[0]), "r"(a[1]), "r"(a[2]), "r"(a[3]), "r"(b[0]), "r"(b[1]));
}
__device__ __forceinline__ void mma16(float* c, const uint32_t* a, const uint32_t* b) {
    asm volatile(
        "mma.sync.aligned.m16n8k16.row.col.f32.f16.f16.f32 "
        "{%0,%1,%2,%3}, {%4,%5,%6,%7}, {%8,%9}, {%0,%1,%2,%3};"
        : "+f"(c[0]), "+f"(c[1]), "+f"(c[2]), "+f"(c[3])
        : "r"(a[0]), "r"(a[1]), "r"(a[2]), "r"(a[3]), "r"(b[0]), "r"(b[1]));
}
__device__ __forceinline__ float sigmoidf_fast(float x) {
    return __fdividef(1.0f, 1.0f + __expf(-x));
}
__device__ __forceinline__ float tanhf_fast(float x) {
    return fmaf(2.0f, __fdividef(1.0f, 1.0f + __expf(-2.0f * x)), -1.0f);
}

// ---------------- setup kernels ----------------
__global__ void conv_all(const float* __restrict__ zs, const float* __restrict__ W1,
                         const float* __restrict__ W2, const float* __restrict__ W3,
                         const float* __restrict__ Wih) {
    int i = blockIdx.x * 256 + threadIdx.x;
    const float* s; float *hi, *lo; int off;
    if      (i < 1048576) { s = zs;  hi = g_xhi;  lo = g_xlo;  off = i; }
    else if (i < 1179648) { s = W1;  hi = g_w1h;  lo = g_w1l;  off = i - 1048576; }
    else if (i < 1310720) { s = W2;  hi = g_w2h;  lo = g_w2l;  off = i - 1179648; }
    else if (i < 1343488) { s = W3;  hi = g_w3h;  lo = g_w3l;  off = i - 1310720; }
    else                  { s = Wih; hi = g_wihh; lo = g_wihl; off = i - 1343488; }
    float x = s[off];
    float h = f2tf_f(x);
    hi[off] = h;
    lo[off] = f2tf_f(x - h);
}
__global__ void conv_whh(const float* __restrict__ whh) {
    int k = threadIdx.x, r = blockIdx.x;                 // r 0..1023
    int jb8 = r >> 7, g = (r >> 5) & 3, j = r & 31;
    int gr = g * 256 + jb8 * 32 + j;
    g_whhc[r * 256 + k] = __float2half(whh[(size_t)gr * 256 + k]);
}
__global__ void init_state() {
    int i = blockIdx.x * 256 + threadIdx.x;   // 0 .. 1048575
    g_c[i] = 0.0f;
    g_ht[i] = __float2half(0.0f);
}

// ================= split-tf32 GEMM (MLP), 256 threads, 128x128 tile =========
#define SG_STRIDE 36
#define SG_HALF   (128 * SG_STRIDE * 4)   // 18432
#define SG_STAGE  (4 * SG_HALF)           // 73728
#define SG_SMEM   (3 * SG_STAGE)          // 221184
#define SG_GS     133

__device__ __forceinline__ void sg_issue(char* sm, int st,
    const float* Ahi, const float* Alo, const float* Bhi, const float* Blo,
    int aBase, int bBase, int K, int tid)
{
    uint32_t base = smem_u32(sm + (st % 3) * SG_STAGE);
    const int k0 = st * 32;
    const int srow = tid >> 3, sk4 = (tid & 7) << 2;
    #pragma unroll
    for (int i = 0; i < 4; i++) {
        int row = i * 32 + srow;
        uint32_t d = base + (uint32_t)(row * SG_STRIDE + sk4) * 4;
        size_t ao = (size_t)(aBase + row) * K + k0 + sk4;
        size_t bo = (size_t)(bBase + row) * K + k0 + sk4;
        cp16(d,               Ahi + ao);
        cp16(d + SG_HALF,     Alo + ao);
        cp16(d + 2 * SG_HALF, Bhi + bo);
        cp16(d + 3 * SG_HALF, Blo + bo);
    }
    cp_commit();
}

__global__ void __launch_bounds__(256, 1) mma_gemm_split(
    const float* __restrict__ Ahi, const float* __restrict__ Alo,
    const float* __restrict__ Bhi, const float* __restrict__ Blo,
    const float* __restrict__ bias, const float* __restrict__ bias2,
    float* __restrict__ Chi, float* __restrict__ Clo,
    int M, int N, int K, int relu, int transC)
{
    extern __shared__ char sm[];
    const int tid = threadIdx.x;
    const int wid = tid >> 5, lane = tid & 31;
    const int wm = wid & 3, wn = wid >> 2;
    const int bm = blockIdx.y * 128, bn = blockIdx.x * 128;
    const int NC = K >> 5;

    float acc[2][8][4];
    #pragma unroll
    for (int mi = 0; mi < 2; mi++)
        #pragma unroll
        for (int ni = 0; ni < 8; ni++)
            #pragma unroll
            for (int v = 0; v < 4; v++) acc[mi][ni][v] = 0.0f;

    sg_issue(sm, 0, Ahi, Alo, Bhi, Blo, bm, bn, K, tid);
    sg_issue(sm, 1, Ahi, Alo, Bhi, Blo, bm, bn, K, tid);

    const int ar = wm * 32 + (lane >> 2);
    const int bc = wn * 64 + (lane >> 2);
    const int q  = lane & 3;

    #pragma unroll 1
    for (int ch = 0; ch < NC; ch++) {
        if (ch == NC - 1) cp_wait0(); else cp_wait1();
        __syncthreads();
        if (ch + 2 < NC) sg_issue(sm, ch + 2, Ahi, Alo, Bhi, Blo, bm, bn, K, tid);
        const uint32_t* Ah = (const uint32_t*)(sm + (ch % 3) * SG_STAGE);
        const uint32_t* Al = Ah + SG_HALF / 4;
        const uint32_t* Bh = Ah + 2 * SG_HALF / 4;
        const uint32_t* Bl = Ah + 3 * SG_HALF / 4;
        #pragma unroll
        for (int kk = 0; kk < 4; kk++) {
            const int kb = kk * 8 + q;
            uint32_t ah[2][4], al[2][4], bh[8][2], bl[8][2];
            #pragma unroll
            for (int mi = 0; mi < 2; mi++) {
                const int r0 = (ar + mi * 16) * SG_STRIDE;
                const int r8 = (ar + mi * 16 + 8) * SG_STRIDE;
                ah[mi][0] = Ah[r0 + kb]; ah[mi][1] = Ah[r8 + kb];
                ah[mi][2] = Ah[r0 + kb + 4]; ah[mi][3] = Ah[r8 + kb + 4];
                al[mi][0] = Al[r0 + kb]; al[mi][1] = Al[r8 + kb];
                al[mi][2] = Al[r0 + kb + 4]; al[mi][3] = Al[r8 + kb + 4];
            }
            #pragma unroll
            for (int ni = 0; ni < 8; ni++) {
                const int rB = (bc + ni * 8) * SG_STRIDE;
                bh[ni][0] = Bh[rB + kb]; bh[ni][1] = Bh[rB + kb + 4];
                bl[ni][0] = Bl[rB + kb]; bl[ni][1] = Bl[rB + kb + 4];
            }
            #pragma unroll
            for (int mi = 0; mi < 2; mi++)
                #pragma unroll
                for (int ni = 0; ni < 8; ni++) {
                    mma8(acc[mi][ni], ah[mi], bl[ni]);
                    mma8(acc[mi][ni], al[mi], bh[ni]);
                    mma8(acc[mi][ni], ah[mi], bh[ni]);
                }
        }
    }
    __syncthreads();

    {
        float* gs = (float*)sm;
        const int grow = wm * 32 + (lane >> 2);
        const int gcol = wn * 64 + ((lane & 3) << 1);
        #pragma unroll
        for (int mi = 0; mi < 2; mi++)
            #pragma unroll
            for (int ni = 0; ni < 8; ni++) {
                int r = grow + mi * 16, cc = gcol + ni * 8;
                gs[r * SG_GS + cc]           = acc[mi][ni][0];
                gs[r * SG_GS + cc + 1]       = acc[mi][ni][1];
                gs[(r + 8) * SG_GS + cc]     = acc[mi][ni][2];
                gs[(r + 8) * SG_GS + cc + 1] = acc[mi][ni][3];
            }
    }
    __syncthreads();

    const float* gs = (const float*)sm;
    if (!transC) {
        #pragma unroll
        for (int i = 0; i < 16; i++) {
            int row = i * 8 + wid;
            #pragma unroll
            for (int cc = 0; cc < 4; cc++) {
                int col = cc * 32 + lane;
                float bv = bias[bn + col];
                if (bias2) bv += bias2[bn + col];
                float v = gs[row * SG_GS + col] + bv;
                if (relu) v = fmaxf(v, 0.0f);
                size_t o = (size_t)(bm + row) * N + bn + col;
                if (Clo) {
                    float h = f2tf_f(v);
                    Chi[o] = h;
                    Clo[o] = f2tf_f(v - h);
                } else Chi[o] = v;
            }
        }
    } else {
        #pragma unroll
        for (int i = 0; i < 16; i++) {
            int col = i * 8 + wid;
            float bv = bias[bn + col];
            if (bias2) bv += bias2[bn + col];
            #pragma unroll
            for (int cc = 0; cc < 4; cc++) {
                int row = cc * 32 + lane;
                float v = gs[row * SG_GS + col] + bv;
                if (relu) v = fmaxf(v, 0.0f);
                Chi[(size_t)(bn + col) * M + bm + row] = v;
            }
        }
    }
}

// ============ persistent clustered LSTM: all 50 steps in one launch =========
// grid (8,16), cluster (8,1,1) = one bm group (256 batch rows) per cluster.
// Each CTA: N-tile = 128 gate cols (32 hidden x 4 gates), M = 256 rows, K=256 fp16.
// Whh tile resident in smem. Cross-CTA dependency (h cols) synced by
// barrier.cluster each step; bm groups are fully independent.
#define PB_BCH  18432                       // B chunk: 128 rows x 36 words x 4
#define PB_A    (4 * PB_BCH)                // 73728: A stages start
#define PB_AST  36864                       // A stage: 256 rows x 36 words x 4
#define PB_GS   PB_A                        // gate buffer aliases A stages (68096 <= 110592)
#define PB_HS   (PB_A + 3 * PB_AST)         // 184320
#define PB_SMEM (PB_HS + 256 * 33 * 4)      // 218112

__device__ __forceinline__ void pa_issue(char* sm, int st, int bm, int tid) {
    uint32_t base = smem_u32(sm + PB_A + (st % 3) * PB_AST);
    const int k0 = st * 64;                     // halves
    const int srow = tid >> 3, skw = (tid & 7) << 2;
    #pragma unroll
    for (int i = 0; i < 4; i++) {
        int row = i * 64 + srow;
        cp16(base + (uint32_t)(row * 36 + skw) * 4,
             g_ht + (size_t)(bm + row) * HID + k0 + skw * 2);
    }
    cp_commit();
}

__global__ void __launch_bounds__(512, 1) __cluster_dims__(8, 1, 1)
lstm_persist(float* __restrict__ out)
{
    extern __shared__ char sm[];
    const int tid  = threadIdx.x;
    const int wid  = tid >> 5;
    const int lane = tid & 31;
    const int wm   = wid & 7, wn = wid >> 3;   // 8 x 2 warp grid (32x64 tiles)
    const int bm   = blockIdx.y * 256;
    const int jbc  = blockIdx.x * 32;          // hidden col base
    const int bBase = blockIdx.x * 128;        // g_whhc row base

    // ---- load resident B (4 chunks) ----
    {
        const int srow = tid >> 3, skw = (tid & 7) << 2;
        #pragma unroll
        for (int ch = 0; ch < 4; ch++) {
            uint32_t base = smem_u32(sm + ch * PB_BCH);
            #pragma unroll
            for (int i = 0; i < 2; i++) {
                int row = i * 64 + srow;
                cp16(base + (uint32_t)(row * 36 + skw) * 4,
                     g_whhc + (size_t)(bBase + row) * HID + ch * 64 + skw * 2);
            }
        }
        cp_commit(); cp_wait0();
    }
    __syncthreads();

    const int ar = wm * 32 + (lane >> 2);
    const int bc = wn * 64 + (lane >> 2);
    const int q  = lane & 3;

    #pragma unroll 1
    for (int t = 0; t < T_STEPS; t++) {
        float acc[2][8][4];
        #pragma unroll
        for (int mi = 0; mi < 2; mi++)
            #pragma unroll
            for (int ni = 0; ni < 8; ni++)
                #pragma unroll
                for (int v = 0; v < 4; v++) acc[mi][ni][v] = 0.0f;

        pa_issue(sm, 0, bm, tid);
        pa_issue(sm, 1, bm, tid);

        #pragma unroll 1
        for (int ch = 0; ch < 4; ch++) {
            if (ch == 3) cp_wait0(); else cp_wait1();
            __syncthreads();
            if (ch + 2 < 4) pa_issue(sm, ch + 2, bm, tid);
            const uint32_t* As = (const uint32_t*)(sm + PB_A + (ch % 3) * PB_AST);
            const uint32_t* Bs = (const uint32_t*)(sm + ch * PB_BCH);
            #pragma unroll
            for (int ks = 0; ks < 4; ks++) {
                const int kb = ks * 8 + q;
                uint32_t a[2][4], b[8][2];
                #pragma unroll
                for (int mi = 0; mi < 2; mi++) {
                    const int r0 = (ar + mi * 16) * 36;
                    const int r8 = (ar + mi * 16 + 8) * 36;
                    a[mi][0] = As[r0 + kb];
                    a[mi][1] = As[r8 + kb];
                    a[mi][2] = As[r0 + kb + 4];
                    a[mi][3] = As[r8 + kb + 4];
                }
                #pragma unroll
                for (int ni = 0; ni < 8; ni++) {
                    const int rB = (bc + ni * 8) * 36;
                    b[ni][0] = Bs[rB + kb];
                    b[ni][1] = Bs[rB + kb + 4];
                }
                #pragma unroll
                for (int mi = 0; mi < 2; mi++)
                    #pragma unroll
                    for (int ni = 0; ni < 8; ni++)
                        mma16(acc[mi][ni], a[mi], b[ni]);
            }
        }
        __syncthreads();

        // ---- 2-pass epilogue (gate buffer 128 rows, aliases A stages) ----
        float* gsw = (float*)(sm + PB_GS);
        float* hsm = (float*)(sm + PB_HS);
        #pragma unroll 1
        for (int p = 0; p < 2; p++) {
            if ((wm >> 2) == p) {
                const int grow = (wm & 3) * 32 + (lane >> 2);
                const int gcol = wn * 64 + ((lane & 3) << 1);
                #pragma unroll
                for (int mi = 0; mi < 2; mi++)
                    #pragma unroll
                    for (int ni = 0; ni < 8; ni++) {
                        int r = grow + mi * 16, cc = gcol + ni * 8;
                        gsw[r * 133 + cc]           = acc[mi][ni][0];
                        gsw[r * 133 + cc + 1]       = acc[mi][ni][1];
                        gsw[(r + 8) * 133 + cc]     = acc[mi][ni][2];
                        gsw[(r + 8) * 133 + cc + 1] = acc[mi][ni][3];
                    }
            }
            __syncthreads();
            {
                const int rloc = tid & 127;
                const int jgrp = tid >> 7;       // 0..3
                const int brow = bm + p * 128 + rloc;
                #pragma unroll
                for (int i = 0; i < 8; i++) {
                    const int jj = jgrp * 8 + i;
                    float gi = gsw[rloc * 133 + jj]      + g_xp[(size_t)(      jbc + jj) * BATCH + brow];
                    float gf = gsw[rloc * 133 + 32 + jj] + g_xp[(size_t)(256 + jbc + jj) * BATCH + brow];
                    float gg = gsw[rloc * 133 + 64 + jj] + g_xp[(size_t)(512 + jbc + jj) * BATCH + brow];
                    float go = gsw[rloc * 133 + 96 + jj] + g_xp[(size_t)(768 + jbc + jj) * BATCH + brow];
                    float cp = g_c[(size_t)(jbc + jj) * BATCH + brow];
                    float vi = sigmoidf_fast(gi);
                    float vf = sigmoidf_fast(gf);
                    float vg = tanhf_fast(gg);
                    float vo = sigmoidf_fast(go);
                    float cn = vf * cp + vi * vg;
                    g_c[(size_t)(jbc + jj) * BATCH + brow] = cn;
                    hsm[(p * 128 + rloc) * 33 + jj] = vo * tanhf_fast(cn);
                }
            }
            __syncthreads();
        }

        // ---- coalesced h writes: out (fp32 strided) + g_ht (fp16) ----
        #pragma unroll
        for (int i = 0; i < 16; i++) {
            int row = i * 16 + wid;
            float v = hsm[row * 33 + lane];
            out[(size_t)(bm + row) * HSTR + (size_t)t * HID + jbc + lane] = v;
            g_ht[(size_t)(bm + row) * HID + jbc + lane] = __float2half(v);
        }

        // ---- cluster barrier: h cols visible to the 7 sibling CTAs ----
        __threadfence();
        asm volatile("barrier.cluster.arrive.aligned;" ::: "memory");
        asm volatile("barrier.cluster.wait.aligned;" ::: "memory");
    }
}

// ---------------- launch ----------------
extern "C" void kernel_launch(void* const* d_in, const int* in_sizes, int n_in,
                              void* d_out, int out_size)
{
    const float* zs  = (const float*)d_in[0];
    const float* W1  = (const float*)d_in[1];
    const float* b1  = (const float*)d_in[2];
    const float* W2  = (const float*)d_in[3];
    const float* b2  = (const float*)d_in[4];
    const float* W3  = (const float*)d_in[5];
    const float* b3  = (const float*)d_in[6];
    const float* Wih = (const float*)d_in[7];
    const float* Whh = (const float*)d_in[8];
    const float* bih = (const float*)d_in[9];
    const float* bhh = (const float*)d_in[10];
    float* out = (float*)d_out;

    float *xhi, *xlo, *w1h, *w1l, *w2h, *w2l, *w3h, *w3l, *wihh, *wihl;
    float *h1h, *h1l, *h2h, *h2l, *z1h, *z1l, *xp;
    cudaGetSymbolAddress((void**)&xhi,  g_xhi);
    cudaGetSymbolAddress((void**)&xlo,  g_xlo);
    cudaGetSymbolAddress((void**)&w1h,  g_w1h);
    cudaGetSymbolAddress((void**)&w1l,  g_w1l);
    cudaGetSymbolAddress((void**)&w2h,  g_w2h);
    cudaGetSymbolAddress((void**)&w2l,  g_w2l);
    cudaGetSymbolAddress((void**)&w3h,  g_w3h);
    cudaGetSymbolAddress((void**)&w3l,  g_w3l);
    cudaGetSymbolAddress((void**)&wihh, g_wihh);
    cudaGetSymbolAddress((void**)&wihl, g_wihl);
    cudaGetSymbolAddress((void**)&h1h,  g_h1h);
    cudaGetSymbolAddress((void**)&h1l,  g_h1l);
    cudaGetSymbolAddress((void**)&h2h,  g_h2h);
    cudaGetSymbolAddress((void**)&h2l,  g_h2l);
    cudaGetSymbolAddress((void**)&z1h,  g_z1h);
    cudaGetSymbolAddress((void**)&z1l,  g_z1l);
    cudaGetSymbolAddress((void**)&xp,   g_xp);

    cudaFuncSetAttribute(mma_gemm_split,
                         cudaFuncAttributeMaxDynamicSharedMemorySize, SG_SMEM);
    cudaFuncSetAttribute(lstm_persist,
                         cudaFuncAttributeMaxDynamicSharedMemorySize, PB_SMEM);

    // setup
    conv_all<<<5760, 256>>>(zs, W1, W2, W3, Wih);
    conv_whh<<<1024, 256>>>(Whh);
    init_state<<<4096, 256>>>();

    // MLP (split-tf32, fp32-grade accuracy)
    mma_gemm_split<<<dim3(4, 32), 256, SG_SMEM>>>(xhi, xlo, w1h, w1l, b1, nullptr,
                                                  h1h, h1l, BATCH, 512, 256, 1, 0);
    mma_gemm_split<<<dim3(2, 32), 256, SG_SMEM>>>(h1h, h1l, w2h, w2l, b2, nullptr,
                                                  h2h, h2l, BATCH, 256, 512, 1, 0);
    mma_gemm_split<<<dim3(1, 32), 256, SG_SMEM>>>(h2h, h2l, w3h, w3l, b3, nullptr,
                                                  z1h, z1l, BATCH, 128, 256, 0, 0);
    // x_part fp32 transposed (includes b_ih + b_hh)
    mma_gemm_split<<<dim3(8, 32), 256, SG_SMEM>>>(z1h, z1l, wihh, wihl, bih, bhh,
                                                  xp, nullptr, BATCH, 1024, 128, 0, 1);

    // all 50 LSTM steps in one persistent clustered launch
    lstm_persist<<<dim3(8, 16), 512, PB_SMEM>>>(out);
}

// round 12
// speedup vs baseline: 1.6209x; 1.6209x over previous
#include <cuda_runtime.h>
#include <cuda_fp16.h>
#include <cstdint>

#define BATCH 4096
#define T_STEPS 50
#define HID 256
#define HSTR (T_STEPS * HID)   // out row stride: 12800 floats

// ---------------- scratch (no allocations allowed) ----------------
__device__ float g_xhi[BATCH * 256],  g_xlo[BATCH * 256];
__device__ float g_w1h[512 * 256],    g_w1l[512 * 256];
__device__ float g_w2h[256 * 512],    g_w2l[256 * 512];
__device__ float g_w3h[128 * 256],    g_w3l[128 * 256];
__device__ float g_wihh[1024 * 128],  g_wihl[1024 * 128];
__device__ float g_h1h[BATCH * 512],  g_h1l[BATCH * 512];
__device__ float g_h2h[BATCH * 256],  g_h2l[BATCH * 256];
__device__ float g_z1h[BATCH * 128],  g_z1l[BATCH * 128];
__device__ float g_xp[1024 * BATCH];          // fp32 TRANSPOSED [1024][4096] (incl. biases)
__device__ float g_c [256  * BATCH];          // fp32 TRANSPOSED [256][4096]
__device__ __half g_ht[BATCH * 256];          // fp16 compact h_{t-1}
__device__ __half g_whhc[1024 * 256];         // fp16 permuted Whh: r' = jb8*128 + g*32 + j

// ---------------- helpers ----------------
__device__ __forceinline__ uint32_t f2tf(float x) {
    uint32_t r;
    asm("cvt.rna.tf32.f32 %0, %1;" : "=r"(r) : "f"(x));
    return r;
}
__device__ __forceinline__ float f2tf_f(float x) { return __uint_as_float(f2tf(x)); }
__device__ __forceinline__ uint32_t smem_u32(const void* p) {
    uint32_t a;
    asm("{ .reg .u64 t; cvta.to.shared.u64 t, %1; cvt.u32.u64 %0, t; }" : "=r"(a) : "l"(p));
    return a;
}
__device__ __forceinline__ void cp16(uint32_t d, const void* s) {
    asm volatile("cp.async.cg.shared.global [%0], [%1], 16;" :: "r"(d), "l"(s));
}
__device__ __forceinline__ void cp_commit() { asm volatile("cp.async.commit_group;"); }
__device__ __forceinline__ void cp_wait1()  { asm volatile("cp.async.wait_group 1;" ::: "memory"); }
__device__ __forceinline__ void cp_wait0()  { asm volatile("cp.async.wait_group 0;" ::: "memory"); }
__device__ __forceinline__ void mma8(float* c, const uint32_t* a, const uint32_t* b) {
    asm volatile(
        "mma.sync.aligned.m16n8k8.row.col.f32.tf32.tf32.f32 "
        "{%0,%1,%2,%3}, {%4,%5,%6,%7}, {%8,%9}, {%0,%1,%2,%3};"
        : "+f"(c[0]), "+f"(c[1]), "+f"(c[2]), "+f"(c[3])
        : "r"(a[0]), "r"(a[1]), "r"(a[2]), "r"(a[3]), "r"(b[0]), "r"(b[1]));
}
__device__ __forceinline__ void mma16(float* c, const uint32_t* a, const uint32_t* b) {
    asm volatile(
        "mma.sync.aligned.m16n8k16.row.col.f32.f16.f16.f32 "
        "{%0,%1,%2,%3}, {%4,%5,%6,%7}, {%8,%9}, {%0,%1,%2,%3};"
        : "+f"(c[0]), "+f"(c[1]), "+f"(c[2]), "+f"(c[3])
        : "r"(a[0]), "r"(a[1]), "r"(a[2]), "r"(a[3]), "r"(b[0]), "r"(b[1]));
}
__device__ __forceinline__ float sigmoidf_fast(float x) {
    return __fdividef(1.0f, 1.0f + __expf(-x));
}
__device__ __forceinline__ float tanhf_fast(float x) {
    return fmaf(2.0f, __fdividef(1.0f, 1.0f + __expf(-2.0f * x)), -1.0f);
}

// ---------------- setup kernels ----------------
__global__ void conv_all(const float* __restrict__ zs, const float* __restrict__ W1,
                         const float* __restrict__ W2, const float* __restrict__ W3,
                         const float* __restrict__ Wih) {
    int i = blockIdx.x * 256 + threadIdx.x;
    const float* s; float *hi, *lo; int off;
    if      (i < 1048576) { s = zs;  hi = g_xhi;  lo = g_xlo;  off = i; }
    else if (i < 1179648) { s = W1;  hi = g_w1h;  lo = g_w1l;  off = i - 1048576; }
    else if (i < 1310720) { s = W2;  hi = g_w2h;  lo = g_w2l;  off = i - 1179648; }
    else if (i < 1343488) { s = W3;  hi = g_w3h;  lo = g_w3l;  off = i - 1310720; }
    else                  { s = Wih; hi = g_wihh; lo = g_wihl; off = i - 1343488; }
    float x = s[off];
    float h = f2tf_f(x);
    hi[off] = h;
    lo[off] = f2tf_f(x - h);
}
__global__ void conv_whh(const float* __restrict__ whh) {
    int k = threadIdx.x, r = blockIdx.x;                 // r 0..1023
    int jb8 = r >> 7, g = (r >> 5) & 3, j = r & 31;
    int gr = g * 256 + jb8 * 32 + j;
    g_whhc[r * 256 + k] = __float2half(whh[(size_t)gr * 256 + k]);
}
__global__ void init_state() {
    int i = blockIdx.x * 256 + threadIdx.x;   // 0 .. 1048575
    g_c[i] = 0.0f;
    g_ht[i] = __float2half(0.0f);
}

// ================= split-tf32 GEMM (MLP), 256 threads, 128x128 tile =========
#define SG_STRIDE 36
#define SG_HALF   (128 * SG_STRIDE * 4)   // 18432
#define SG_STAGE  (4 * SG_HALF)           // 73728
#define SG_SMEM   (3 * SG_STAGE)          // 221184
#define SG_GS     133

__device__ __forceinline__ void sg_issue(char* sm, int st,
    const float* Ahi, const float* Alo, const float* Bhi, const float* Blo,
    int aBase, int bBase, int K, int tid)
{
    uint32_t base = smem_u32(sm + (st % 3) * SG_STAGE);
    const int k0 = st * 32;
    const int srow = tid >> 3, sk4 = (tid & 7) << 2;
    #pragma unroll
    for (int i = 0; i < 4; i++) {
        int row = i * 32 + srow;
        uint32_t d = base + (uint32_t)(row * SG_STRIDE + sk4) * 4;
        size_t ao = (size_t)(aBase + row) * K + k0 + sk4;
        size_t bo = (size_t)(bBase + row) * K + k0 + sk4;
        cp16(d,               Ahi + ao);
        cp16(d + SG_HALF,     Alo + ao);
        cp16(d + 2 * SG_HALF, Bhi + bo);
        cp16(d + 3 * SG_HALF, Blo + bo);
    }
    cp_commit();
}

__global__ void __launch_bounds__(256, 1) mma_gemm_split(
    const float* __restrict__ Ahi, const float* __restrict__ Alo,
    const float* __restrict__ Bhi, const float* __restrict__ Blo,
    const float* __restrict__ bias, const float* __restrict__ bias2,
    float* __restrict__ Chi, float* __restrict__ Clo,
    int M, int N, int K, int relu, int transC)
{
    extern __shared__ char sm[];
    const int tid = threadIdx.x;
    const int wid = tid >> 5, lane = tid & 31;
    const int wm = wid & 3, wn = wid >> 2;
    const int bm = blockIdx.y * 128, bn = blockIdx.x * 128;
    const int NC = K >> 5;

    float acc[2][8][4];
    #pragma unroll
    for (int mi = 0; mi < 2; mi++)
        #pragma unroll
        for (int ni = 0; ni < 8; ni++)
            #pragma unroll
            for (int v = 0; v < 4; v++) acc[mi][ni][v] = 0.0f;

    sg_issue(sm, 0, Ahi, Alo, Bhi, Blo, bm, bn, K, tid);
    sg_issue(sm, 1, Ahi, Alo, Bhi, Blo, bm, bn, K, tid);

    const int ar = wm * 32 + (lane >> 2);
    const int bc = wn * 64 + (lane >> 2);
    const int q  = lane & 3;

    #pragma unroll 1
    for (int ch = 0; ch < NC; ch++) {
        if (ch == NC - 1) cp_wait0(); else cp_wait1();
        __syncthreads();
        if (ch + 2 < NC) sg_issue(sm, ch + 2, Ahi, Alo, Bhi, Blo, bm, bn, K, tid);
        const uint32_t* Ah = (const uint32_t*)(sm + (ch % 3) * SG_STAGE);
        const uint32_t* Al = Ah + SG_HALF / 4;
        const uint32_t* Bh = Ah + 2 * SG_HALF / 4;
        const uint32_t* Bl = Ah + 3 * SG_HALF / 4;
        #pragma unroll
        for (int kk = 0; kk < 4; kk++) {
            const int kb = kk * 8 + q;
            uint32_t ah[2][4], al[2][4], bh[8][2], bl[8][2];
            #pragma unroll
            for (int mi = 0; mi < 2; mi++) {
                const int r0 = (ar + mi * 16) * SG_STRIDE;
                const int r8 = (ar + mi * 16 + 8) * SG_STRIDE;
                ah[mi][0] = Ah[r0 + kb]; ah[mi][1] = Ah[r8 + kb];
                ah[mi][2] = Ah[r0 + kb + 4]; ah[mi][3] = Ah[r8 + kb + 4];
                al[mi][0] = Al[r0 + kb]; al[mi][1] = Al[r8 + kb];
                al[mi][2] = Al[r0 + kb + 4]; al[mi][3] = Al[r8 + kb + 4];
            }
            #pragma unroll
            for (int ni = 0; ni < 8; ni++) {
                const int rB = (bc + ni * 8) * SG_STRIDE;
                bh[ni][0] = Bh[rB + kb]; bh[ni][1] = Bh[rB + kb + 4];
                bl[ni][0] = Bl[rB + kb]; bl[ni][1] = Bl[rB + kb + 4];
            }
            #pragma unroll
            for (int mi = 0; mi < 2; mi++)
                #pragma unroll
                for (int ni = 0; ni < 8; ni++) {
                    mma8(acc[mi][ni], ah[mi], bl[ni]);
                    mma8(acc[mi][ni], al[mi], bh[ni]);
                    mma8(acc[mi][ni], ah[mi], bh[ni]);
                }
        }
    }
    __syncthreads();

    {
        float* gs = (float*)sm;
        const int grow = wm * 32 + (lane >> 2);
        const int gcol = wn * 64 + ((lane & 3) << 1);
        #pragma unroll
        for (int mi = 0; mi < 2; mi++)
            #pragma unroll
            for (int ni = 0; ni < 8; ni++) {
                int r = grow + mi * 16, cc = gcol + ni * 8;
                gs[r * SG_GS + cc]           = acc[mi][ni][0];
                gs[r * SG_GS + cc + 1]       = acc[mi][ni][1];
                gs[(r + 8) * SG_GS + cc]     = acc[mi][ni][2];
                gs[(r + 8) * SG_GS + cc + 1] = acc[mi][ni][3];
            }
    }
    __syncthreads();

    const float* gs = (const float*)sm;
    if (!transC) {
        #pragma unroll
        for (int i = 0; i < 16; i++) {
            int row = i * 8 + wid;
            #pragma unroll
            for (int cc = 0; cc < 4; cc++) {
                int col = cc * 32 + lane;
                float bv = bias[bn + col];
                if (bias2) bv += bias2[bn + col];
                float v = gs[row * SG_GS + col] + bv;
                if (relu) v = fmaxf(v, 0.0f);
                size_t o = (size_t)(bm + row) * N + bn + col;
                if (Clo) {
                    float h = f2tf_f(v);
                    Chi[o] = h;
                    Clo[o] = f2tf_f(v - h);
                } else Chi[o] = v;
            }
        }
    } else {
        #pragma unroll
        for (int i = 0; i < 16; i++) {
            int col = i * 8 + wid;
            float bv = bias[bn + col];
            if (bias2) bv += bias2[bn + col];
            #pragma unroll
            for (int cc = 0; cc < 4; cc++) {
                int row = cc * 32 + lane;
                float v = gs[row * SG_GS + col] + bv;
                if (relu) v = fmaxf(v, 0.0f);
                Chi[(size_t)(bn + col) * M + bm + row] = v;
            }
        }
    }
}

// ===== fp16 LSTM step v2: 256 threads, 128x128 tile, 2 CTAs/SM overlap ======
// gates[128 batch rows][128 cols=(g,j)] = h_{t-1}(fp16) @ Whh_perm(fp16)^T, K=256.
// 3-stage cp.async, k-chunk 32 halves (16 words/row, stride 20 words).
// Fragment bank = (20r + 8ks + q) mod 32 -> all 32 distinct, conflict-free.
#define S2_W     20                         // words per staged row
#define S2_HALF  (128 * S2_W * 4)           // 10240
#define S2_STAGE (2 * S2_HALF)              // 20480 ; 3 stages = 61440
#define S2_GS    133
#define S2_HS    (128 * S2_GS * 4)          // 68096 (gs aliases stages)
#define S2_SMEM  (S2_HS + 128 * 33 * 4)     // 84992

__device__ __forceinline__ void st2_issue(char* sm, int st, int bm, int bBase, int tid)
{
    uint32_t base = smem_u32(sm + (st % 3) * S2_STAGE);
    const int k0 = st * 32;                       // halves
    const int srow = tid >> 2;                    // 0..63
    const int skw  = (tid & 3) << 2;              // word offset 0,4,8,12
    #pragma unroll
    for (int i = 0; i < 2; i++) {
        int row = i * 64 + srow;
        cp16(base + (uint32_t)(row * S2_W + skw) * 4,
             g_ht + (size_t)(bm + row) * HID + k0 + skw * 2);
        cp16(base + S2_HALF + (uint32_t)(row * S2_W + skw) * 4,
             g_whhc + (size_t)(bBase + row) * HID + k0 + skw * 2);
    }
    cp_commit();
}

__global__ void __launch_bounds__(256, 2)
lstm_step(float* __restrict__ out, int t)
{
    extern __shared__ char sm[];
    const int tid  = threadIdx.x;
    const int wid  = tid >> 5;
    const int lane = tid & 31;
    const int wm   = wid & 3, wn = wid >> 2;   // 4 x 2 warp grid (32x64 tiles)
    const int bm   = blockIdx.y * 128;
    const int jbc  = blockIdx.x * 32;          // hidden col base
    const int bBase = blockIdx.x * 128;        // g_whhc row base

    if (t > 0) {
        float acc[2][8][4];
        #pragma unroll
        for (int mi = 0; mi < 2; mi++)
            #pragma unroll
            for (int ni = 0; ni < 8; ni++)
                #pragma unroll
                for (int v = 0; v < 4; v++) acc[mi][ni][v] = 0.0f;

        st2_issue(sm, 0, bm, bBase, tid);
        st2_issue(sm, 1, bm, bBase, tid);

        const int ar = wm * 32 + (lane >> 2);
        const int bc = wn * 64 + (lane >> 2);
        const int q  = lane & 3;

        #pragma unroll 1
        for (int ch = 0; ch < 8; ch++) {
            if (ch == 7) cp_wait0(); else cp_wait1();
            __syncthreads();
            if (ch + 2 < 8) st2_issue(sm, ch + 2, bm, bBase, tid);
            const uint32_t* As = (const uint32_t*)(sm + (ch % 3) * S2_STAGE);
            const uint32_t* Bs = As + S2_HALF / 4;
            #pragma unroll
            for (int ks = 0; ks < 2; ks++) {
                const int kb = ks * 8 + q;
                uint32_t a[2][4], b[8][2];
                #pragma unroll
                for (int mi = 0; mi < 2; mi++) {
                    const int r0 = (ar + mi * 16) * S2_W;
                    const int r8 = (ar + mi * 16 + 8) * S2_W;
                    a[mi][0] = As[r0 + kb];
                    a[mi][1] = As[r8 + kb];
                    a[mi][2] = As[r0 + kb + 4];
                    a[mi][3] = As[r8 + kb + 4];
                }
                #pragma unroll
                for (int ni = 0; ni < 8; ni++) {
                    const int rB = (bc + ni * 8) * S2_W;
                    b[ni][0] = Bs[rB + kb];
                    b[ni][1] = Bs[rB + kb + 4];
                }
                #pragma unroll
                for (int mi = 0; mi < 2; mi++)
                    #pragma unroll
                    for (int ni = 0; ni < 8; ni++)
                        mma16(acc[mi][ni], a[mi], b[ni]);
            }
        }
        __syncthreads();

        // stage gates: gs[128][133], local col = g*32 + j
        float* gs = (float*)sm;
        const int grow = wm * 32 + (lane >> 2);
        const int gcol = wn * 64 + ((lane & 3) << 1);
        #pragma unroll
        for (int mi = 0; mi < 2; mi++)
            #pragma unroll
            for (int ni = 0; ni < 8; ni++) {
                int r = grow + mi * 16, cc = gcol + ni * 8;
                gs[r * S2_GS + cc]           = acc[mi][ni][0];
                gs[r * S2_GS + cc + 1]       = acc[mi][ni][1];
                gs[(r + 8) * S2_GS + cc]     = acc[mi][ni][2];
                gs[(r + 8) * S2_GS + cc + 1] = acc[mi][ni][3];
            }
        __syncthreads();
    }

    // ---------------- LSTM cell epilogue ----------------
    const float* gs = (const float*)sm;
    float* hsm = (float*)(sm + S2_HS);
    const int rloc = tid & 127;
    const int chalf = tid >> 7;          // 0 or 1
    const int brow = bm + rloc;

    #pragma unroll
    for (int i = 0; i < 16; i++) {
        const int jj = chalf * 16 + i;   // 0..31
        float gi, gf, gg, go;
        if (t > 0) {
            gi = gs[rloc * S2_GS + jj];
            gf = gs[rloc * S2_GS + 32 + jj];
            gg = gs[rloc * S2_GS + 64 + jj];
            go = gs[rloc * S2_GS + 96 + jj];
        } else {
            gi = gf = gg = go = 0.0f;
        }
        gi += g_xp[(size_t)(      jbc + jj) * BATCH + brow];
        gf += g_xp[(size_t)(256 + jbc + jj) * BATCH + brow];
        gg += g_xp[(size_t)(512 + jbc + jj) * BATCH + brow];
        go += g_xp[(size_t)(768 + jbc + jj) * BATCH + brow];
        float cp = (t > 0) ? g_c[(size_t)(jbc + jj) * BATCH + brow] : 0.0f;
        float vi = sigmoidf_fast(gi);
        float vf = sigmoidf_fast(gf);
        float vg = tanhf_fast(gg);
        float vo = sigmoidf_fast(go);
        float cn = vf * cp + vi * vg;
        g_c[(size_t)(jbc + jj) * BATCH + brow] = cn;
        hsm[rloc * 33 + jj] = vo * tanhf_fast(cn);
    }
    __syncthreads();

    // coalesced h writes: out (fp32 strided) + g_ht (fp16 compact)
    #pragma unroll
    for (int i = 0; i < 16; i++) {
        int row = i * 8 + wid;
        float v = hsm[row * 33 + lane];
        out[(size_t)(bm + row) * HSTR + (size_t)t * HID + jbc + lane] = v;
        g_ht[(size_t)(bm + row) * HID + jbc + lane] = __float2half(v);
    }
}

// ---------------- launch ----------------
extern "C" void kernel_launch(void* const* d_in, const int* in_sizes, int n_in,
                              void* d_out, int out_size)
{
    const float* zs  = (const float*)d_in[0];
    const float* W1  = (const float*)d_in[1];
    const float* b1  = (const float*)d_in[2];
    const float* W2  = (const float*)d_in[3];
    const float* b2  = (const float*)d_in[4];
    const float* W3  = (const float*)d_in[5];
    const float* b3  = (const float*)d_in[6];
    const float* Wih = (const float*)d_in[7];
    const float* Whh = (const float*)d_in[8];
    const float* bih = (const float*)d_in[9];
    const float* bhh = (const float*)d_in[10];
    float* out = (float*)d_out;

    float *xhi, *xlo, *w1h, *w1l, *w2h, *w2l, *w3h, *w3l, *wihh, *wihl;
    float *h1h, *h1l, *h2h, *h2l, *z1h, *z1l, *xp;
    cudaGetSymbolAddress((void**)&xhi,  g_xhi);
    cudaGetSymbolAddress((void**)&xlo,  g_xlo);
    cudaGetSymbolAddress((void**)&w1h,  g_w1h);
    cudaGetSymbolAddress((void**)&w1l,  g_w1l);
    cudaGetSymbolAddress((void**)&w2h,  g_w2h);
    cudaGetSymbolAddress((void**)&w2l,  g_w2l);
    cudaGetSymbolAddress((void**)&w3h,  g_w3h);
    cudaGetSymbolAddress((void**)&w3l,  g_w3l);
    cudaGetSymbolAddress((void**)&wihh, g_wihh);
    cudaGetSymbolAddress((void**)&wihl, g_wihl);
    cudaGetSymbolAddress((void**)&h1h,  g_h1h);
    cudaGetSymbolAddress((void**)&h1l,  g_h1l);
    cudaGetSymbolAddress((void**)&h2h,  g_h2h);
    cudaGetSymbolAddress((void**)&h2l,  g_h2l);
    cudaGetSymbolAddress((void**)&z1h,  g_z1h);
    cudaGetSymbolAddress((void**)&z1l,  g_z1l);
    cudaGetSymbolAddress((void**)&xp,   g_xp);

    cudaFuncSetAttribute(mma_gemm_split,
                         cudaFuncAttributeMaxDynamicSharedMemorySize, SG_SMEM);
    cudaFuncSetAttribute(lstm_step,
                         cudaFuncAttributeMaxDynamicSharedMemorySize, S2_SMEM);

    // setup
    conv_all<<<5760, 256>>>(zs, W1, W2, W3, Wih);
    conv_whh<<<1024, 256>>>(Whh);
    init_state<<<4096, 256>>>();

    // MLP (split-tf32, fp32-grade accuracy)
    mma_gemm_split<<<dim3(4, 32), 256, SG_SMEM>>>(xhi, xlo, w1h, w1l, b1, nullptr,
                                                  h1h, h1l, BATCH, 512, 256, 1, 0);
    mma_gemm_split<<<dim3(2, 32), 256, SG_SMEM>>>(h1h, h1l, w2h, w2l, b2, nullptr,
                                                  h2h, h2l, BATCH, 256, 512, 1, 0);
    mma_gemm_split<<<dim3(1, 32), 256, SG_SMEM>>>(h2h, h2l, w3h, w3l, b3, nullptr,
                                                  z1h, z1l, BATCH, 128, 256, 0, 0);
    // x_part fp32 transposed (includes b_ih + b_hh)
    mma_gemm_split<<<dim3(8, 32), 256, SG_SMEM>>>(z1h, z1l, wihh, wihl, bih, bhh,
                                                  xp, nullptr, BATCH, 1024, 128, 0, 1);

    // 50 fp16 tensor-core LSTM steps (256 CTAs, 2 per SM)
    for (int t = 0; t < T_STEPS; t++)
        lstm_step<<<dim3(8, 32), 256, S2_SMEM>>>(out, t);
}

// round 13
// speedup vs baseline: 1.8951x; 1.1691x over previous
#include <cuda_runtime.h>
#include <cuda_fp16.h>
#include <cstdint>

#define BATCH 4096
#define T_STEPS 50
#define HID 256
#define HSTR (T_STEPS * HID)   // out row stride: 12800 floats

// ---------------- scratch (no allocations allowed) ----------------
__device__ float g_xhi[BATCH * 256],  g_xlo[BATCH * 256];
__device__ float g_w1h[512 * 256],    g_w1l[512 * 256];
__device__ float g_w2h[256 * 512],    g_w2l[256 * 512];
__device__ float g_w3h[128 * 256],    g_w3l[128 * 256];
__device__ float g_wihh[1024 * 128],  g_wihl[1024 * 128];
__device__ float g_h1h[BATCH * 512],  g_h1l[BATCH * 512];
__device__ float g_h2h[BATCH * 256],  g_h2l[BATCH * 256];
__device__ float g_z1h[BATCH * 128],  g_z1l[BATCH * 128];
__device__ __half g_xph[1024 * BATCH];        // fp16 TRANSPOSED x_part [1024][4096] (incl. biases)
__device__ float g_c [256  * BATCH];          // fp32 TRANSPOSED [256][4096]
__device__ __half g_ht[BATCH * 256];          // fp16 compact h_{t-1}
__device__ __half g_whhc[1024 * 256];         // fp16 permuted Whh: r' = jb8*128 + g*32 + j

// ---------------- helpers ----------------
__device__ __forceinline__ uint32_t f2tf(float x) {
    uint32_t r;
    asm("cvt.rna.tf32.f32 %0, %1;" : "=r"(r) : "f"(x));
    return r;
}
__device__ __forceinline__ float f2tf_f(float x) { return __uint_as_float(f2tf(x)); }
__device__ __forceinline__ uint32_t smem_u32(const void* p) {
    uint32_t a;
    asm("{ .reg .u64 t; cvta.to.shared.u64 t, %1; cvt.u32.u64 %0, t; }" : "=r"(a) : "l"(p));
    return a;
}
__device__ __forceinline__ void cp16(uint32_t d, const void* s) {
    asm volatile("cp.async.cg.shared.global [%0], [%1], 16;" :: "r"(d), "l"(s));
}
__device__ __forceinline__ void cp_commit() { asm volatile("cp.async.commit_group;"); }
__device__ __forceinline__ void cp_wait1()  { asm volatile("cp.async.wait_group 1;" ::: "memory"); }
__device__ __forceinline__ void cp_wait0()  { asm volatile("cp.async.wait_group 0;" ::: "memory"); }
__device__ __forceinline__ void mma8(float* c, const uint32_t* a, const uint32_t* b) {
    asm volatile(
        "mma.sync.aligned.m16n8k8.row.col.f32.tf32.tf32.f32 "
        "{%0,%1,%2,%3}, {%4,%5,%6,%7}, {%8,%9}, {%0,%1,%2,%3};"
        : "+f"(c[0]), "+f"(c[1]), "+f"(c[2]), "+f"(c[3])
        : "r"(a[0]), "r"(a[1]), "r"(a[2]), "r"(a[3]), "r"(b[0]), "r"(b[1]));
}
__device__ __forceinline__ void mma16(float* c, const uint32_t* a, const uint32_t* b) {
    asm volatile(
        "mma.sync.aligned.m16n8k16.row.col.f32.f16.f16.f32 "
        "{%0,%1,%2,%3}, {%4,%5,%6,%7}, {%8,%9}, {%0,%1,%2,%3};"
        : "+f"(c[0]), "+f"(c[1]), "+f"(c[2]), "+f"(c[3])
        : "r"(a[0]), "r"(a[1]), "r"(a[2]), "r"(a[3]), "r"(b[0]), "r"(b[1]));
}
__device__ __forceinline__ float sigmoidf_fast(float x) {
    return __fdividef(1.0f, 1.0f + __expf(-x));
}
__device__ __forceinline__ float tanhf_fast(float x) {
    return fmaf(2.0f, __fdividef(1.0f, 1.0f + __expf(-2.0f * x)), -1.0f);
}

// ---------------- setup kernels ----------------
__global__ void conv_all(const float* __restrict__ zs, const float* __restrict__ W1,
                         const float* __restrict__ W2, const float* __restrict__ W3,
                         const float* __restrict__ Wih) {
    int i = blockIdx.x * 256 + threadIdx.x;
    const float* s; float *hi, *lo; int off;
    if      (i < 1048576) { s = zs;  hi = g_xhi;  lo = g_xlo;  off = i; }
    else if (i < 1179648) { s = W1;  hi = g_w1h;  lo = g_w1l;  off = i - 1048576; }
    else if (i < 1310720) { s = W2;  hi = g_w2h;  lo = g_w2l;  off = i - 1179648; }
    else if (i < 1343488) { s = W3;  hi = g_w3h;  lo = g_w3l;  off = i - 1310720; }
    else                  { s = Wih; hi = g_wihh; lo = g_wihl; off = i - 1343488; }
    float x = s[off];
    float h = f2tf_f(x);
    hi[off] = h;
    lo[off] = f2tf_f(x - h);
}
__global__ void conv_whh(const float* __restrict__ whh) {
    int k = threadIdx.x, r = blockIdx.x;                 // r 0..1023
    int jb8 = r >> 7, g = (r >> 5) & 3, j = r & 31;
    int gr = g * 256 + jb8 * 32 + j;
    g_whhc[r * 256 + k] = __float2half(whh[(size_t)gr * 256 + k]);
}
__global__ void init_state() {
    int i = blockIdx.x * 256 + threadIdx.x;   // 0 .. 1048575
    g_c[i] = 0.0f;
    g_ht[i] = __float2half(0.0f);
}

// ================= split-tf32 GEMM (MLP), 256 threads, 128x128 tile =========
#define SG_STRIDE 36
#define SG_HALF   (128 * SG_STRIDE * 4)   // 18432
#define SG_STAGE  (4 * SG_HALF)           // 73728
#define SG_SMEM   (3 * SG_STAGE)          // 221184
#define SG_GS     133

__device__ __forceinline__ void sg_issue(char* sm, int st,
    const float* Ahi, const float* Alo, const float* Bhi, const float* Blo,
    int aBase, int bBase, int K, int tid)
{
    uint32_t base = smem_u32(sm + (st % 3) * SG_STAGE);
    const int k0 = st * 32;
    const int srow = tid >> 3, sk4 = (tid & 7) << 2;
    #pragma unroll
    for (int i = 0; i < 4; i++) {
        int row = i * 32 + srow;
        uint32_t d = base + (uint32_t)(row * SG_STRIDE + sk4) * 4;
        size_t ao = (size_t)(aBase + row) * K + k0 + sk4;
        size_t bo = (size_t)(bBase + row) * K + k0 + sk4;
        cp16(d,               Ahi + ao);
        cp16(d + SG_HALF,     Alo + ao);
        cp16(d + 2 * SG_HALF, Bhi + bo);
        cp16(d + 3 * SG_HALF, Blo + bo);
    }
    cp_commit();
}

// transC != 0 -> output written as fp16 (to g_xph), transposed [N][M]
__global__ void __launch_bounds__(256, 1) mma_gemm_split(
    const float* __restrict__ Ahi, const float* __restrict__ Alo,
    const float* __restrict__ Bhi, const float* __restrict__ Blo,
    const float* __restrict__ bias, const float* __restrict__ bias2,
    float* __restrict__ Chi, float* __restrict__ Clo,
    int M, int N, int K, int relu, int transC)
{
    extern __shared__ char sm[];
    const int tid = threadIdx.x;
    const int wid = tid >> 5, lane = tid & 31;
    const int wm = wid & 3, wn = wid >> 2;
    const int bm = blockIdx.y * 128, bn = blockIdx.x * 128;
    const int NC = K >> 5;

    float acc[2][8][4];
    #pragma unroll
    for (int mi = 0; mi < 2; mi++)
        #pragma unroll
        for (int ni = 0; ni < 8; ni++)
            #pragma unroll
            for (int v = 0; v < 4; v++) acc[mi][ni][v] = 0.0f;

    sg_issue(sm, 0, Ahi, Alo, Bhi, Blo, bm, bn, K, tid);
    sg_issue(sm, 1, Ahi, Alo, Bhi, Blo, bm, bn, K, tid);

    const int ar = wm * 32 + (lane >> 2);
    const int bc = wn * 64 + (lane >> 2);
    const int q  = lane & 3;

    #pragma unroll 1
    for (int ch = 0; ch < NC; ch++) {
        if (ch == NC - 1) cp_wait0(); else cp_wait1();
        __syncthreads();
        if (ch + 2 < NC) sg_issue(sm, ch + 2, Ahi, Alo, Bhi, Blo, bm, bn, K, tid);
        const uint32_t* Ah = (const uint32_t*)(sm + (ch % 3) * SG_STAGE);
        const uint32_t* Al = Ah + SG_HALF / 4;
        const uint32_t* Bh = Ah + 2 * SG_HALF / 4;
        const uint32_t* Bl = Ah + 3 * SG_HALF / 4;
        #pragma unroll
        for (int kk = 0; kk < 4; kk++) {
            const int kb = kk * 8 + q;
            uint32_t ah[2][4], al[2][4], bh[8][2], bl[8][2];
            #pragma unroll
            for (int mi = 0; mi < 2; mi++) {
                const int r0 = (ar + mi * 16) * SG_STRIDE;
                const int r8 = (ar + mi * 16 + 8) * SG_STRIDE;
                ah[mi][0] = Ah[r0 + kb]; ah[mi][1] = Ah[r8 + kb];
                ah[mi][2] = Ah[r0 + kb + 4]; ah[mi][3] = Ah[r8 + kb + 4];
                al[mi][0] = Al[r0 + kb]; al[mi][1] = Al[r8 + kb];
                al[mi][2] = Al[r0 + kb + 4]; al[mi][3] = Al[r8 + kb + 4];
            }
            #pragma unroll
            for (int ni = 0; ni < 8; ni++) {
                const int rB = (bc + ni * 8) * SG_STRIDE;
                bh[ni][0] = Bh[rB + kb]; bh[ni][1] = Bh[rB + kb + 4];
                bl[ni][0] = Bl[rB + kb]; bl[ni][1] = Bl[rB + kb + 4];
            }
            #pragma unroll
            for (int mi = 0; mi < 2; mi++)
                #pragma unroll
                for (int ni = 0; ni < 8; ni++) {
                    mma8(acc[mi][ni], ah[mi], bl[ni]);
                    mma8(acc[mi][ni], al[mi], bh[ni]);
                    mma8(acc[mi][ni], ah[mi], bh[ni]);
                }
        }
    }
    __syncthreads();

    {
        float* gs = (float*)sm;
        const int grow = wm * 32 + (lane >> 2);
        const int gcol = wn * 64 + ((lane & 3) << 1);
        #pragma unroll
        for (int mi = 0; mi < 2; mi++)
            #pragma unroll
            for (int ni = 0; ni < 8; ni++) {
                int r = grow + mi * 16, cc = gcol + ni * 8;
                gs[r * SG_GS + cc]           = acc[mi][ni][0];
                gs[r * SG_GS + cc + 1]       = acc[mi][ni][1];
                gs[(r + 8) * SG_GS + cc]     = acc[mi][ni][2];
                gs[(r + 8) * SG_GS + cc + 1] = acc[mi][ni][3];
            }
    }
    __syncthreads();

    const float* gs = (const float*)sm;
    if (!transC) {
        #pragma unroll
        for (int i = 0; i < 16; i++) {
            int row = i * 8 + wid;
            #pragma unroll
            for (int cc = 0; cc < 4; cc++) {
                int col = cc * 32 + lane;
                float bv = bias[bn + col];
                if (bias2) bv += bias2[bn + col];
                float v = gs[row * SG_GS + col] + bv;
                if (relu) v = fmaxf(v, 0.0f);
                size_t o = (size_t)(bm + row) * N + bn + col;
                if (Clo) {
                    float h = f2tf_f(v);
                    Chi[o] = h;
                    Clo[o] = f2tf_f(v - h);
                } else Chi[o] = v;
            }
        }
    } else {
        __half* C16 = (__half*)Chi;
        #pragma unroll
        for (int i = 0; i < 16; i++) {
            int col = i * 8 + wid;
            float bv = bias[bn + col];
            if (bias2) bv += bias2[bn + col];
            #pragma unroll
            for (int cc = 0; cc < 4; cc++) {
                int row = cc * 32 + lane;
                float v = gs[row * SG_GS + col] + bv;
                if (relu) v = fmaxf(v, 0.0f);
                C16[(size_t)(bn + col) * M + bm + row] = __float2half(v);
            }
        }
    }
}

// ===== fp16 LSTM step (R10 shape): 512 threads, 256x128 tile, grid (8,16) ===
// gates = h_{t-1}(fp16) @ Whh_perm(fp16)^T, K=256, 4 chunks x 64 halves,
// 3-stage cp.async. Each stage group ALSO carries 1/4 of this CTA's xp slice
// (fp16, 64 KB) into smem, completing under the GEMM.
#define SH_W    36                         // words per staged row (72 halves)
#define ST_A    (256 * SH_W * 4)           // 36864
#define ST_B    (128 * SH_W * 4)           // 18432
#define ST_STAGE (ST_A + ST_B)             // 55296 ; 3 stages = 165888
#define ST_GS   133                        // gate buffer stride (aliases stages)
#define XP_OFF  (3 * ST_STAGE)             // 165888
#define ST_SMEM (XP_OFF + 128 * 256 * 2)   // 231424

__device__ __forceinline__ void xp_piece(uint32_t xpb, int p, int bm, int jbc, int tid) {
    // piece p: local cols [p*32, p*32+32), each col = 256 halves = 32 x 16B
    #pragma unroll
    for (int g2 = 0; g2 < 2; g2++) {
        int v = g2 * 512 + tid;                     // 0..1023
        int lcol = p * 32 + (v >> 5);               // local gate-col 0..127
        int seg  = v & 31;
        int grow = ((lcol >> 5) << 8) + jbc + (lcol & 31);   // xp global row
        cp16(xpb + (uint32_t)(lcol * 512 + seg * 16),
             g_xph + (size_t)grow * BATCH + bm + seg * 8);
    }
}

__device__ __forceinline__ void st_issue(char* sm, int st, int bm, int bBase,
                                         int jbc, int tid)
{
    uint32_t base = smem_u32(sm + (st % 3) * ST_STAGE);
    const int k0 = st * 64;                       // halves
    const int srow = tid >> 3;                    // 0..63
    const int skw  = (tid & 7) << 2;              // word offset (8 halves each)
    #pragma unroll
    for (int i = 0; i < 4; i++) {
        int row = i * 64 + srow;
        cp16(base + (uint32_t)(row * SH_W + skw) * 4,
             g_ht + (size_t)(bm + row) * HID + k0 + skw * 2);
    }
    #pragma unroll
    for (int i = 0; i < 2; i++) {
        int row = i * 64 + srow;
        cp16(base + ST_A + (uint32_t)(row * SH_W + skw) * 4,
             g_whhc + (size_t)(bBase + row) * HID + k0 + skw * 2);
    }
    xp_piece(smem_u32(sm + XP_OFF), st, bm, jbc, tid);
    cp_commit();
}

__global__ void __launch_bounds__(512, 1)
lstm_step(float* __restrict__ out, int t)
{
    extern __shared__ char sm[];
    const int tid  = threadIdx.x;
    const int wid  = tid >> 5;
    const int lane = tid & 31;
    const int wm   = wid & 7, wn = wid >> 3;   // 8 x 2 warp grid (32x64 tiles)
    const int bm   = blockIdx.y * 256;
    const int jbc  = blockIdx.x * 32;          // hidden col base
    const int bBase = blockIdx.x * 128;        // g_whhc row base

    if (t > 0) {
        float acc[2][8][4];
        #pragma unroll
        for (int mi = 0; mi < 2; mi++)
            #pragma unroll
            for (int ni = 0; ni < 8; ni++)
                #pragma unroll
                for (int v = 0; v < 4; v++) acc[mi][ni][v] = 0.0f;

        st_issue(sm, 0, bm, bBase, jbc, tid);
        st_issue(sm, 1, bm, bBase, jbc, tid);

        const int ar = wm * 32 + (lane >> 2);
        const int bc = wn * 64 + (lane >> 2);
        const int q  = lane & 3;

        #pragma unroll 1
        for (int ch = 0; ch < 4; ch++) {
            if (ch == 3) cp_wait0(); else cp_wait1();
            __syncthreads();
            if (ch + 2 < 4) st_issue(sm, ch + 2, bm, bBase, jbc, tid);
            const uint32_t* As = (const uint32_t*)(sm + (ch % 3) * ST_STAGE);
            const uint32_t* Bs = As + ST_A / 4;
            #pragma unroll
            for (int ks = 0; ks < 4; ks++) {
                const int kb = ks * 8 + q;
                uint32_t a[2][4], b[8][2];
                #pragma unroll
                for (int mi = 0; mi < 2; mi++) {
                    const int r0 = (ar + mi * 16) * SH_W;
                    const int r8 = (ar + mi * 16 + 8) * SH_W;
                    a[mi][0] = As[r0 + kb];
                    a[mi][1] = As[r8 + kb];
                    a[mi][2] = As[r0 + kb + 4];
                    a[mi][3] = As[r8 + kb + 4];
                }
                #pragma unroll
                for (int ni = 0; ni < 8; ni++) {
                    const int rB = (bc + ni * 8) * SH_W;
                    b[ni][0] = Bs[rB + kb];
                    b[ni][1] = Bs[rB + kb + 4];
                }
                #pragma unroll
                for (int mi = 0; mi < 2; mi++)
                    #pragma unroll
                    for (int ni = 0; ni < 8; ni++)
                        mma16(acc[mi][ni], a[mi], b[ni]);
            }
        }
        __syncthreads();

        // stage gates: gs[256][133], local col = g*32 + j
        float* gs = (float*)sm;
        const int grow = wm * 32 + (lane >> 2);
        const int gcol = wn * 64 + ((lane & 3) << 1);
        #pragma unroll
        for (int mi = 0; mi < 2; mi++)
            #pragma unroll
            for (int ni = 0; ni < 8; ni++) {
                int r = grow + mi * 16, cc = gcol + ni * 8;
                gs[r * ST_GS + cc]           = acc[mi][ni][0];
                gs[r * ST_GS + cc + 1]       = acc[mi][ni][1];
                gs[(r + 8) * ST_GS + cc]     = acc[mi][ni][2];
                gs[(r + 8) * ST_GS + cc + 1] = acc[mi][ni][3];
            }
        __syncthreads();
    } else {
        // t == 0: only the xp slice is needed
        uint32_t xpb = smem_u32(sm + XP_OFF);
        #pragma unroll
        for (int p = 0; p < 4; p++) xp_piece(xpb, p, bm, jbc, tid);
        cp_commit(); cp_wait0();
        __syncthreads();
    }

    // ---------------- LSTM cell epilogue ----------------
    const float* gs = (const float*)sm;
    const __half* xps = (const __half*)(sm + XP_OFF);
    const int rloc = tid & 255;
    const int chalf = tid >> 8;          // 0 or 1
    const int brow = bm + rloc;

    float cp[16], hv[16];
    #pragma unroll
    for (int i = 0; i < 16; i++) {
        int jj = chalf * 16 + i;
        cp[i] = (t > 0) ? g_c[(size_t)(jbc + jj) * BATCH + brow] : 0.0f;
    }
    #pragma unroll
    for (int i = 0; i < 16; i++) {
        const int jj = chalf * 16 + i;   // 0..31
        float gi = __half2float(xps[(size_t)(      jj) * 256 + rloc]);
        float gf = __half2float(xps[(size_t)(32  + jj) * 256 + rloc]);
        float gg = __half2float(xps[(size_t)(64  + jj) * 256 + rloc]);
        float go = __half2float(xps[(size_t)(96  + jj) * 256 + rloc]);
        if (t > 0) {
            gi += gs[rloc * ST_GS + jj];
            gf += gs[rloc * ST_GS + 32 + jj];
            gg += gs[rloc * ST_GS + 64 + jj];
            go += gs[rloc * ST_GS + 96 + jj];
        }
        float vi = sigmoidf_fast(gi);
        float vf = sigmoidf_fast(gf);
        float vg = tanhf_fast(gg);
        float vo = sigmoidf_fast(go);
        float cn = vf * cp[i] + vi * vg;
        g_c[(size_t)(jbc + jj) * BATCH + brow] = cn;
        hv[i] = vo * tanhf_fast(cn);
    }
    __syncthreads();

    // h staging reuses the gate-buffer region (all gs reads done)
    float* hs = (float*)sm;
    #pragma unroll
    for (int i = 0; i < 16; i++)
        hs[rloc * 33 + chalf * 16 + i] = hv[i];
    __syncthreads();

    // coalesced h writes: out (fp32 strided) + g_ht (fp16 compact)
    #pragma unroll
    for (int i = 0; i < 16; i++) {
        int row = i * 16 + wid;
        float v = hs[row * 33 + lane];
        out[(size_t)(bm + row) * HSTR + (size_t)t * HID + jbc + lane] = v;
        g_ht[(size_t)(bm + row) * HID + jbc + lane] = __float2half(v);
    }
}

// ---------------- launch ----------------
extern "C" void kernel_launch(void* const* d_in, const int* in_sizes, int n_in,
                              void* d_out, int out_size)
{
    const float* zs  = (const float*)d_in[0];
    const float* W1  = (const float*)d_in[1];
    const float* b1  = (const float*)d_in[2];
    const float* W2  = (const float*)d_in[3];
    const float* b2  = (const float*)d_in[4];
    const float* W3  = (const float*)d_in[5];
    const float* b3  = (const float*)d_in[6];
    const float* Wih = (const float*)d_in[7];
    const float* Whh = (const float*)d_in[8];
    const float* bih = (const float*)d_in[9];
    const float* bhh = (const float*)d_in[10];
    float* out = (float*)d_out;

    float *xhi, *xlo, *w1h, *w1l, *w2h, *w2l, *w3h, *w3l, *wihh, *wihl;
    float *h1h, *h1l, *h2h, *h2l, *z1h, *z1l;
    void  *xph;
    cudaGetSymbolAddress((void**)&xhi,  g_xhi);
    cudaGetSymbolAddress((void**)&xlo,  g_xlo);
    cudaGetSymbolAddress((void**)&w1h,  g_w1h);
    cudaGetSymbolAddress((void**)&w1l,  g_w1l);
    cudaGetSymbolAddress((void**)&w2h,  g_w2h);
    cudaGetSymbolAddress((void**)&w2l,  g_w2l);
    cudaGetSymbolAddress((void**)&w3h,  g_w3h);
    cudaGetSymbolAddress((void**)&w3l,  g_w3l);
    cudaGetSymbolAddress((void**)&wihh, g_wihh);
    cudaGetSymbolAddress((void**)&wihl, g_wihl);
    cudaGetSymbolAddress((void**)&h1h,  g_h1h);
    cudaGetSymbolAddress((void**)&h1l,  g_h1l);
    cudaGetSymbolAddress((void**)&h2h,  g_h2h);
    cudaGetSymbolAddress((void**)&h2l,  g_h2l);
    cudaGetSymbolAddress((void**)&z1h,  g_z1h);
    cudaGetSymbolAddress((void**)&z1l,  g_z1l);
    cudaGetSymbolAddress(&xph,          g_xph);

    cudaFuncSetAttribute(mma_gemm_split,
                         cudaFuncAttributeMaxDynamicSharedMemorySize, SG_SMEM);
    cudaFuncSetAttribute(lstm_step,
                         cudaFuncAttributeMaxDynamicSharedMemorySize, ST_SMEM);

    // setup
    conv_all<<<5760, 256>>>(zs, W1, W2, W3, Wih);
    conv_whh<<<1024, 256>>>(Whh);
    init_state<<<4096, 256>>>();

    // MLP (split-tf32, fp32-grade accuracy)
    mma_gemm_split<<<dim3(4, 32), 256, SG_SMEM>>>(xhi, xlo, w1h, w1l, b1, nullptr,
                                                  h1h, h1l, BATCH, 512, 256, 1, 0);
    mma_gemm_split<<<dim3(2, 32), 256, SG_SMEM>>>(h1h, h1l, w2h, w2l, b2, nullptr,
                                                  h2h, h2l, BATCH, 256, 512, 1, 0);
    mma_gemm_split<<<dim3(1, 32), 256, SG_SMEM>>>(h2h, h2l, w3h, w3l, b3, nullptr,
                                                  z1h, z1l, BATCH, 128, 256, 0, 0);
    // x_part fp16 transposed (includes b_ih + b_hh)
    mma_gemm_split<<<dim3(8, 32), 256, SG_SMEM>>>(z1h, z1l, wihh, wihl, bih, bhh,
                                                  (float*)xph, nullptr, BATCH, 1024, 128, 0, 1);

    // 50 fp16 tensor-core LSTM steps (single wave: 8 x 16 = 128 CTAs)
    for (int t = 0; t < T_STEPS; t++)
        lstm_step<<<dim3(8, 16), 512, ST_SMEM>>>(out, t);
}